// round 7
// baseline (speedup 1.0000x reference)
#include <cuda_runtime.h>
#include <cuda_bf16.h>
#include <cstdint>

#define N_NODES 50000
#define IN_DIM  512
#define HID_DIM 128
#define MAX_E   1000000

// ---------------- scratch (device globals; no allocation allowed) ----------
__device__ float g_h[(size_t)N_NODES * 128];     // 25.6 MB
__device__ float g_tmp[(size_t)N_NODES * 128];   // 25.6 MB
__device__ float g_inv_out[N_NODES];
__device__ float g_inv_in[N_NODES];
__device__ int   g_deg_out[N_NODES];
__device__ int   g_deg_in[N_NODES];
__device__ int   g_row_ptr[N_NODES + 1];
__device__ int   g_cursor[N_NODES];
__device__ int   g_edge_src[MAX_E];
// pre-split weights (tf32 hi/lo)
__device__ uint32_t g_W1_hi[IN_DIM * 128],  g_W1_lo[IN_DIM * 128];
__device__ uint32_t g_W2_hi[HID_DIM * 128], g_W2_lo[HID_DIM * 128];

// ---------------- tf32 helpers ---------------------------------------------
__device__ __forceinline__ uint32_t f2tf32(float x) {
    uint32_t r;
    asm("cvt.rna.tf32.f32 %0, %1;" : "=r"(r) : "f"(x));
    return r;
}

__device__ __forceinline__ void split_tf32(float x, uint32_t& hi, uint32_t& lo) {
    hi = f2tf32(x);
    lo = f2tf32(x - __uint_as_float(hi));   // tf32 bits are valid fp32 bits
}

__device__ __forceinline__ void mma_tf32(float c[4],
                                         uint32_t a0, uint32_t a1,
                                         uint32_t a2, uint32_t a3,
                                         uint32_t b0, uint32_t b1) {
    asm volatile(
        "mma.sync.aligned.m16n8k8.row.col.f32.tf32.tf32.f32 "
        "{%0,%1,%2,%3}, {%4,%5,%6,%7}, {%8,%9}, {%0,%1,%2,%3};"
        : "+f"(c[0]), "+f"(c[1]), "+f"(c[2]), "+f"(c[3])
        : "r"(a0), "r"(a1), "r"(a2), "r"(a3), "r"(b0), "r"(b1));
}

// ---------------- weight pre-split (once per launch) -----------------------
__global__ void split_w_kernel(const float* __restrict__ W,
                               uint32_t* __restrict__ hi,
                               uint32_t* __restrict__ lo, int n) {
    int i = blockIdx.x * blockDim.x + threadIdx.x;
    if (i < n) {
        uint32_t h, l;
        split_tf32(W[i], h, l);
        hi[i] = h; lo[i] = l;
    }
}

// ---------------- CSR build ------------------------------------------------
__global__ void zero_deg_kernel() {
    int i = blockIdx.x * blockDim.x + threadIdx.x;
    if (i < N_NODES) { g_deg_out[i] = 0; g_deg_in[i] = 0; }
}

__global__ void hist_kernel(const int* __restrict__ src,
                            const int* __restrict__ dst, int E) {
    int i = blockIdx.x * blockDim.x + threadIdx.x;
    if (i < E) {
        atomicAdd(&g_deg_out[src[i]], 1);
        atomicAdd(&g_deg_in[dst[i]], 1);
    }
}

// single-block chunked exclusive scan of deg_in -> row_ptr, cursor
__global__ void scan_kernel() {
    __shared__ int sums[1024];
    const int n = N_NODES;
    int tid = threadIdx.x;
    int chunk = (n + 1023) >> 10;
    int start = tid * chunk;
    int end = start + chunk; if (end > n) end = n;
    int local = 0;
    for (int i = start; i < end; i++) local += g_deg_in[i];
    sums[tid] = local;
    __syncthreads();
    for (int off = 1; off < 1024; off <<= 1) {
        int v = (tid >= off) ? sums[tid - off] : 0;
        __syncthreads();
        sums[tid] += v;
        __syncthreads();
    }
    int run = (tid == 0) ? 0 : sums[tid - 1];
    for (int i = start; i < end; i++) {
        g_row_ptr[i] = run;
        g_cursor[i]  = run;
        run += g_deg_in[i];
    }
    if (tid == 1023) g_row_ptr[n] = sums[1023];
}

__global__ void fill_kernel(const int* __restrict__ src,
                            const int* __restrict__ dst, int E) {
    int i = blockIdx.x * blockDim.x + threadIdx.x;
    if (i < E) {
        int pos = atomicAdd(&g_cursor[dst[i]], 1);
        g_edge_src[pos] = src[i];
    }
}

__global__ void inv_kernel() {
    int i = blockIdx.x * blockDim.x + threadIdx.x;
    if (i < N_NODES) {
        int dout = g_deg_out[i]; if (dout < 1) dout = 1;
        int din  = g_deg_in[i];  if (din  < 1) din  = 1;
        g_inv_out[i] = rsqrtf((float)dout);
        g_inv_in[i]  = rsqrtf((float)din);
    }
}

// ---------------- tf32x3 GEMM: C[M,128] = (A[M,K] @ W[K,128]) * inv_out ----
// BM=128, BN=128, BK=16. 256 threads = 8 warps, warp grid 2(M) x 4(N),
// warp tile 64x32 = 4x4 m16n8k8 atoms. Error-compensated: hh + hl + lh.
// B (weights) arrive pre-split as tf32 hi/lo.
template <int K>
__global__ __launch_bounds__(256)
void gemm_tf32_kernel(const float* __restrict__ A,
                      const uint32_t* __restrict__ Whi,
                      const uint32_t* __restrict__ Wlo,
                      float* __restrict__ C, int M) {
    constexpr int BM = 128, BK = 16;
    constexpr int AP = 20;    // A row stride (words): conflict-free frag loads
    constexpr int BP = 136;   // B row stride (words)
    __shared__ uint32_t As_hi[BM][AP], As_lo[BM][AP];   // [m][k]
    __shared__ uint32_t Bs_hi[BK][BP], Bs_lo[BK][BP];   // [k][n]

    const int tid  = threadIdx.x;
    const int wid  = tid >> 5;
    const int lane = tid & 31;
    const int gid  = lane >> 2;       // 0..7
    const int tig  = lane & 3;        // 0..3
    const int wm   = (wid & 1) * 64;  // warp M offset
    const int wn   = (wid >> 1) * 32; // warp N offset
    const int row0 = blockIdx.x * BM;

    // global tile-load coords (2 float4/uint4 per thread for each of A, B)
    const int idA0  = tid * 2;
    const int rA[2] = { idA0 >> 2, (idA0 + 1) >> 2 };   // 0..127
    const int cA[2] = { idA0 & 3,  (idA0 + 1) & 3 };    // 0..3  (vec4 idx)
    const int rB[2] = { idA0 >> 5, (idA0 + 1) >> 5 };   // 0..15
    const int cB[2] = { idA0 & 31, (idA0 + 1) & 31 };   // 0..31 (vec4 idx)

    float c[4][4][4];
#pragma unroll
    for (int i = 0; i < 4; i++)
#pragma unroll
        for (int j = 0; j < 4; j++)
#pragma unroll
            for (int q = 0; q < 4; q++) c[i][j][q] = 0.f;

    float4 av[2];
    uint4  bvh[2], bvl[2];
#pragma unroll
    for (int i = 0; i < 2; i++) {
        int gr = row0 + rA[i];
        av[i] = (gr < M) ? *(const float4*)&A[(size_t)gr * K + cA[i] * 4]
                         : make_float4(0.f, 0.f, 0.f, 0.f);
        bvh[i] = *(const uint4*)&Whi[(size_t)rB[i] * 128 + cB[i] * 4];
        bvl[i] = *(const uint4*)&Wlo[(size_t)rB[i] * 128 + cB[i] * 4];
    }

    for (int k0 = 0; k0 < K; k0 += BK) {
        // A: split + store; B: straight copy
#pragma unroll
        for (int i = 0; i < 2; i++) {
            const float va[4] = { av[i].x, av[i].y, av[i].z, av[i].w };
#pragma unroll
            for (int q = 0; q < 4; q++) {
                uint32_t h, l;
                split_tf32(va[q], h, l);
                As_hi[rA[i]][cA[i] * 4 + q] = h;
                As_lo[rA[i]][cA[i] * 4 + q] = l;
            }
            *(uint4*)&Bs_hi[rB[i]][cB[i] * 4] = bvh[i];
            *(uint4*)&Bs_lo[rB[i]][cB[i] * 4] = bvl[i];
        }
        __syncthreads();

        // prefetch next tiles (LDGs overlap MMA body)
        if (k0 + BK < K) {
#pragma unroll
            for (int i = 0; i < 2; i++) {
                int gr = row0 + rA[i];
                av[i] = (gr < M)
                    ? *(const float4*)&A[(size_t)gr * K + (k0 + BK) + cA[i] * 4]
                    : make_float4(0.f, 0.f, 0.f, 0.f);
                bvh[i] = *(const uint4*)&Whi[(size_t)(k0 + BK + rB[i]) * 128 + cB[i] * 4];
                bvl[i] = *(const uint4*)&Wlo[(size_t)(k0 + BK + rB[i]) * 128 + cB[i] * 4];
            }
        }

#pragma unroll
        for (int kk = 0; kk < BK; kk += 8) {
            // A fragments (4 m-atoms)
            uint32_t a_hi[4][4], a_lo[4][4];
#pragma unroll
            for (int i = 0; i < 4; i++) {
                int m0 = wm + i * 16 + gid;
                a_hi[i][0] = As_hi[m0    ][kk + tig];
                a_hi[i][1] = As_hi[m0 + 8][kk + tig];
                a_hi[i][2] = As_hi[m0    ][kk + tig + 4];
                a_hi[i][3] = As_hi[m0 + 8][kk + tig + 4];
                a_lo[i][0] = As_lo[m0    ][kk + tig];
                a_lo[i][1] = As_lo[m0 + 8][kk + tig];
                a_lo[i][2] = As_lo[m0    ][kk + tig + 4];
                a_lo[i][3] = As_lo[m0 + 8][kk + tig + 4];
            }
            // B fragments (4 n-atoms)
            uint32_t b_hi[4][2], b_lo[4][2];
#pragma unroll
            for (int j = 0; j < 4; j++) {
                int n0 = wn + j * 8 + gid;
                b_hi[j][0] = Bs_hi[kk + tig    ][n0];
                b_hi[j][1] = Bs_hi[kk + tig + 4][n0];
                b_lo[j][0] = Bs_lo[kk + tig    ][n0];
                b_lo[j][1] = Bs_lo[kk + tig + 4][n0];
            }
#pragma unroll
            for (int i = 0; i < 4; i++)
#pragma unroll
                for (int j = 0; j < 4; j++) {
                    mma_tf32(c[i][j], a_hi[i][0], a_hi[i][1], a_hi[i][2], a_hi[i][3],
                             b_lo[j][0], b_lo[j][1]);
                    mma_tf32(c[i][j], a_lo[i][0], a_lo[i][1], a_lo[i][2], a_lo[i][3],
                             b_hi[j][0], b_hi[j][1]);
                    mma_tf32(c[i][j], a_hi[i][0], a_hi[i][1], a_hi[i][2], a_hi[i][3],
                             b_hi[j][0], b_hi[j][1]);
                }
        }
        __syncthreads();
    }

    // epilogue: scale by inv_out[row]
#pragma unroll
    for (int i = 0; i < 4; i++) {
        int r0 = row0 + wm + i * 16 + gid;
        int r1 = r0 + 8;
        float s0 = (r0 < M) ? g_inv_out[r0] : 0.f;
        float s1 = (r1 < M) ? g_inv_out[r1] : 0.f;
#pragma unroll
        for (int j = 0; j < 4; j++) {
            int col = wn + j * 8 + tig * 2;
            if (r0 < M)
                *(float2*)&C[(size_t)r0 * 128 + col] =
                    make_float2(c[i][j][0] * s0, c[i][j][1] * s0);
            if (r1 < M)
                *(float2*)&C[(size_t)r1 * 128 + col] =
                    make_float2(c[i][j][2] * s1, c[i][j][3] * s1);
        }
    }
}

// ---------------- CSR gather with fused epilogue ---------------------------
// One warp per destination node; lane owns 4 contiguous floats.
// 8-edge unroll, dual accumulators for deeper MLP + shorter FADD chains.
template <bool RELU>
__global__ void gather_kernel(const float* __restrict__ h,
                              const float* __restrict__ bias,
                              float* __restrict__ out) {
    int node = (blockIdx.x * blockDim.x + threadIdx.x) >> 5;
    int lane = threadIdx.x & 31;
    if (node >= N_NODES) return;

    int beg = g_row_ptr[node];
    int end = g_row_ptr[node + 1];

    float4 acc0 = make_float4(0.f, 0.f, 0.f, 0.f);
    float4 acc1 = make_float4(0.f, 0.f, 0.f, 0.f);
    int i = beg;
    for (; i + 8 <= end; i += 8) {
        int s[8];
#pragma unroll
        for (int q = 0; q < 8; q++) s[q] = g_edge_src[i + q];
        float4 v[8];
#pragma unroll
        for (int q = 0; q < 8; q++)
            v[q] = *(const float4*)&h[(size_t)s[q] * 128 + lane * 4];
        acc0.x += (v[0].x + v[1].x) + (v[2].x + v[3].x);
        acc0.y += (v[0].y + v[1].y) + (v[2].y + v[3].y);
        acc0.z += (v[0].z + v[1].z) + (v[2].z + v[3].z);
        acc0.w += (v[0].w + v[1].w) + (v[2].w + v[3].w);
        acc1.x += (v[4].x + v[5].x) + (v[6].x + v[7].x);
        acc1.y += (v[4].y + v[5].y) + (v[6].y + v[7].y);
        acc1.z += (v[4].z + v[5].z) + (v[6].z + v[7].z);
        acc1.w += (v[4].w + v[5].w) + (v[6].w + v[7].w);
    }
    for (; i < end; i++) {
        int s = g_edge_src[i];
        float4 v = *(const float4*)&h[(size_t)s * 128 + lane * 4];
        acc0.x += v.x; acc0.y += v.y; acc0.z += v.z; acc0.w += v.w;
    }
    acc0.x += acc1.x; acc0.y += acc1.y; acc0.z += acc1.z; acc0.w += acc1.w;

    float sc = g_inv_in[node];
    float4 bb = *(const float4*)&bias[lane * 4];
    float4 o;
    o.x = acc0.x * sc + bb.x;
    o.y = acc0.y * sc + bb.y;
    o.z = acc0.z * sc + bb.z;
    o.w = acc0.w * sc + bb.w;
    if (RELU) {
        o.x = fmaxf(o.x, 0.f); o.y = fmaxf(o.y, 0.f);
        o.z = fmaxf(o.z, 0.f); o.w = fmaxf(o.w, 0.f);
    }
    *(float4*)&out[(size_t)node * 128 + lane * 4] = o;
}

// ---------------- host-side per-encoder driver -----------------------------
static void run_encoder(const float* feat, const int* src, const int* dst,
                        const uint32_t* W1hi, const uint32_t* W1lo,
                        const float* b1,
                        const uint32_t* W2hi, const uint32_t* W2lo,
                        const float* b2,
                        float* z, int E, float* ph, float* ptmp) {
    const int NT = 256;
    const int nblk_nodes  = (N_NODES + NT - 1) / NT;
    const int nblk_edges  = (E + NT - 1) / NT;
    const int gemm_blocks = (N_NODES + 127) / 128;
    const int gather_blocks = (N_NODES * 32 + NT - 1) / NT;

    // CSR build (once per graph, reused by both layers)
    zero_deg_kernel<<<nblk_nodes, NT>>>();
    hist_kernel<<<nblk_edges, NT>>>(src, dst, E);
    scan_kernel<<<1, 1024>>>();
    fill_kernel<<<nblk_edges, NT>>>(src, dst, E);
    inv_kernel<<<nblk_nodes, NT>>>();

    // layer 1
    gemm_tf32_kernel<IN_DIM><<<gemm_blocks, NT>>>(feat, W1hi, W1lo, ph, N_NODES);
    gather_kernel<true><<<gather_blocks, NT>>>(ph, b1, ptmp);

    // layer 2
    gemm_tf32_kernel<HID_DIM><<<gemm_blocks, NT>>>(ptmp, W2hi, W2lo, ph, N_NODES);
    gather_kernel<false><<<gather_blocks, NT>>>(ph, b2, z);
}

extern "C" void kernel_launch(void* const* d_in, const int* in_sizes, int n_in,
                              void* d_out, int out_size) {
    const float* feat1 = (const float*)d_in[0];
    const int*   src1  = (const int*)d_in[1];
    const int*   dst1  = (const int*)d_in[2];
    const float* feat2 = (const float*)d_in[3];
    const int*   src2  = (const int*)d_in[4];
    const int*   dst2  = (const int*)d_in[5];
    const float* feat  = (const float*)d_in[6];
    const int*   src   = (const int*)d_in[7];
    const int*   dst   = (const int*)d_in[8];
    const float* W1    = (const float*)d_in[9];
    const float* b1    = (const float*)d_in[10];
    const float* W2    = (const float*)d_in[11];
    const float* b2    = (const float*)d_in[12];
    float* out = (float*)d_out;

    float *ph = nullptr, *ptmp = nullptr;
    uint32_t *w1h, *w1l, *w2h, *w2l;
    cudaGetSymbolAddress((void**)&ph,  g_h);
    cudaGetSymbolAddress((void**)&ptmp, g_tmp);
    cudaGetSymbolAddress((void**)&w1h, g_W1_hi);
    cudaGetSymbolAddress((void**)&w1l, g_W1_lo);
    cudaGetSymbolAddress((void**)&w2h, g_W2_hi);
    cudaGetSymbolAddress((void**)&w2l, g_W2_lo);

    // pre-split weights once (shared by all 3 encoders)
    split_w_kernel<<<(IN_DIM * 128 + 255) / 256, 256>>>(W1, w1h, w1l, IN_DIM * 128);
    split_w_kernel<<<(HID_DIM * 128 + 255) / 256, 256>>>(W2, w2h, w2l, HID_DIM * 128);

    run_encoder(feat1, src1, dst1, w1h, w1l, b1, w2h, w2l, b2,
                out,                              in_sizes[1], ph, ptmp);
    run_encoder(feat2, src2, dst2, w1h, w1l, b1, w2h, w2l, b2,
                out + (size_t)N_NODES * 128,      in_sizes[4], ph, ptmp);
    run_encoder(feat,  src,  dst,  w1h, w1l, b1, w2h, w2l, b2,
                out + (size_t)2 * N_NODES * 128,  in_sizes[7], ph, ptmp);
}

// round 10
// speedup vs baseline: 1.2449x; 1.2449x over previous
#include <cuda_runtime.h>
#include <cuda_bf16.h>
#include <cstdint>

#define N_NODES 50000
#define IN_DIM  512
#define HID_DIM 128
#define MAX_E   1000000
#define NENC    3

// ---------------- scratch (device globals; no allocation allowed) ----------
__device__ float g_h[(size_t)NENC * N_NODES * 128];     // 76.8 MB
__device__ float g_tmp[(size_t)NENC * N_NODES * 128];   // 76.8 MB
__device__ float g_inv_out[NENC * N_NODES];
__device__ float g_inv_in[NENC * N_NODES];
__device__ int   g_deg_out[NENC * N_NODES];
__device__ int   g_deg_in[NENC * N_NODES];
__device__ int   g_row_ptr[NENC * (N_NODES + 1)];
__device__ int   g_cursor[NENC * N_NODES];
__device__ int   g_edge_src[NENC * MAX_E];
// pre-split weights (tf32 hi/lo)
__device__ uint32_t g_W1_hi[IN_DIM * 128],  g_W1_lo[IN_DIM * 128];
__device__ uint32_t g_W2_hi[HID_DIM * 128], g_W2_lo[HID_DIM * 128];

// per-encoder pointer bundle (passed by value through kernel params)
struct GraphPtrs {
    const int*   src[NENC];
    const int*   dst[NENC];
    int          E[NENC];
};
struct FeatPtrs {
    const float* p[NENC];
};

// ---------------- tf32 helpers ---------------------------------------------
__device__ __forceinline__ uint32_t f2tf32(float x) {
    uint32_t r;
    asm("cvt.rna.tf32.f32 %0, %1;" : "=r"(r) : "f"(x));
    return r;
}

__device__ __forceinline__ void split_tf32(float x, uint32_t& hi, uint32_t& lo) {
    hi = f2tf32(x);
    lo = f2tf32(x - __uint_as_float(hi));   // tf32 bits are valid fp32 bits
}

__device__ __forceinline__ void mma_tf32(float c[4],
                                         uint32_t a0, uint32_t a1,
                                         uint32_t a2, uint32_t a3,
                                         uint32_t b0, uint32_t b1) {
    asm volatile(
        "mma.sync.aligned.m16n8k8.row.col.f32.tf32.tf32.f32 "
        "{%0,%1,%2,%3}, {%4,%5,%6,%7}, {%8,%9}, {%0,%1,%2,%3};"
        : "+f"(c[0]), "+f"(c[1]), "+f"(c[2]), "+f"(c[3])
        : "r"(a0), "r"(a1), "r"(a2), "r"(a3), "r"(b0), "r"(b1));
}

// ---------------- weight pre-split (once per launch) -----------------------
__global__ void split_w_kernel(const float* __restrict__ W,
                               uint32_t* __restrict__ hi,
                               uint32_t* __restrict__ lo, int n) {
    int i = blockIdx.x * blockDim.x + threadIdx.x;
    if (i < n) {
        uint32_t h, l;
        split_tf32(W[i], h, l);
        hi[i] = h; lo[i] = l;
    }
}

// ---------------- CSR build (all 3 graphs in one launch each) --------------
__global__ void zero_deg_kernel() {
    int i = blockIdx.x * blockDim.x + threadIdx.x;
    if (i < NENC * N_NODES) { g_deg_out[i] = 0; g_deg_in[i] = 0; }
}

__global__ void hist_kernel(GraphPtrs gp) {
    int enc = blockIdx.y;
    int i = blockIdx.x * blockDim.x + threadIdx.x;
    if (i < gp.E[enc]) {
        atomicAdd(&g_deg_out[enc * N_NODES + gp.src[enc][i]], 1);
        atomicAdd(&g_deg_in[enc * N_NODES + gp.dst[enc][i]], 1);
    }
}

// one block per graph; chunked exclusive scan of deg_in -> row_ptr, cursor
__global__ void scan_kernel() {
    __shared__ int sums[1024];
    const int enc = blockIdx.x;
    const int* deg = g_deg_in + enc * N_NODES;
    int* rp  = g_row_ptr + enc * (N_NODES + 1);
    int* cur = g_cursor  + enc * N_NODES;

    const int n = N_NODES;
    int tid = threadIdx.x;
    int chunk = (n + 1023) >> 10;
    int start = tid * chunk;
    int end = start + chunk; if (end > n) end = n;
    int local = 0;
    for (int i = start; i < end; i++) local += deg[i];
    sums[tid] = local;
    __syncthreads();
    for (int off = 1; off < 1024; off <<= 1) {
        int v = (tid >= off) ? sums[tid - off] : 0;
        __syncthreads();
        sums[tid] += v;
        __syncthreads();
    }
    int run = (tid == 0) ? 0 : sums[tid - 1];
    for (int i = start; i < end; i++) {
        rp[i]  = run;
        cur[i] = run;
        run += deg[i];
    }
    if (tid == 1023) rp[n] = sums[1023];
}

__global__ void fill_kernel(GraphPtrs gp) {
    int enc = blockIdx.y;
    int i = blockIdx.x * blockDim.x + threadIdx.x;
    if (i < gp.E[enc]) {
        int pos = atomicAdd(&g_cursor[enc * N_NODES + gp.dst[enc][i]], 1);
        g_edge_src[enc * MAX_E + pos] = gp.src[enc][i];
    }
}

__global__ void inv_kernel() {
    int i = blockIdx.x * blockDim.x + threadIdx.x;
    if (i < NENC * N_NODES) {
        int dout = g_deg_out[i]; if (dout < 1) dout = 1;
        int din  = g_deg_in[i];  if (din  < 1) din  = 1;
        g_inv_out[i] = rsqrtf((float)dout);
        g_inv_in[i]  = rsqrtf((float)din);
    }
}

// ---------------- tf32x3 GEMM: C[M,128] = (A[M,K] @ W[K,128]) * inv_out ----
// BM=128, BN=128, BK=16. 256 threads = 8 warps, warp grid 2(M) x 4(N),
// warp tile 64x32 = 4x4 m16n8k8 atoms. Error-compensated: hh + hl + lh.
// blockIdx.y selects the encoder (A pointer, C slab, inv_out slab).
template <int K>
__global__ __launch_bounds__(256)
void gemm_tf32_kernel(FeatPtrs fp,
                      const uint32_t* __restrict__ Whi,
                      const uint32_t* __restrict__ Wlo,
                      float* __restrict__ Cbase, int M) {
    constexpr int BM = 128, BK = 16;
    constexpr int AP = 20;    // A row stride (words): conflict-free frag loads
    constexpr int BP = 136;   // B row stride (words)
    __shared__ uint32_t As_hi[BM][AP], As_lo[BM][AP];   // [m][k]
    __shared__ uint32_t Bs_hi[BK][BP], Bs_lo[BK][BP];   // [k][n]

    const int enc = blockIdx.y;
    const float* __restrict__ A = fp.p[enc];
    float* __restrict__ C = Cbase + (size_t)enc * N_NODES * 128;
    const float* __restrict__ inv_out = g_inv_out + enc * N_NODES;

    const int tid  = threadIdx.x;
    const int wid  = tid >> 5;
    const int lane = tid & 31;
    const int gid  = lane >> 2;       // 0..7
    const int tig  = lane & 3;        // 0..3
    const int wm   = (wid & 1) * 64;  // warp M offset
    const int wn   = (wid >> 1) * 32; // warp N offset
    const int row0 = blockIdx.x * BM;

    // global tile-load coords (2 float4/uint4 per thread for each of A, B)
    const int idA0  = tid * 2;
    const int rA[2] = { idA0 >> 2, (idA0 + 1) >> 2 };   // 0..127
    const int cA[2] = { idA0 & 3,  (idA0 + 1) & 3 };    // 0..3  (vec4 idx)
    const int rB[2] = { idA0 >> 5, (idA0 + 1) >> 5 };   // 0..15
    const int cB[2] = { idA0 & 31, (idA0 + 1) & 31 };   // 0..31 (vec4 idx)

    float c[4][4][4];
#pragma unroll
    for (int i = 0; i < 4; i++)
#pragma unroll
        for (int j = 0; j < 4; j++)
#pragma unroll
            for (int q = 0; q < 4; q++) c[i][j][q] = 0.f;

    float4 av[2];
    uint4  bvh[2], bvl[2];
#pragma unroll
    for (int i = 0; i < 2; i++) {
        int gr = row0 + rA[i];
        av[i] = (gr < M) ? *(const float4*)&A[(size_t)gr * K + cA[i] * 4]
                         : make_float4(0.f, 0.f, 0.f, 0.f);
        bvh[i] = *(const uint4*)&Whi[(size_t)rB[i] * 128 + cB[i] * 4];
        bvl[i] = *(const uint4*)&Wlo[(size_t)rB[i] * 128 + cB[i] * 4];
    }

    for (int k0 = 0; k0 < K; k0 += BK) {
        // A: split + store; B: straight copy
#pragma unroll
        for (int i = 0; i < 2; i++) {
            const float va[4] = { av[i].x, av[i].y, av[i].z, av[i].w };
#pragma unroll
            for (int q = 0; q < 4; q++) {
                uint32_t h, l;
                split_tf32(va[q], h, l);
                As_hi[rA[i]][cA[i] * 4 + q] = h;
                As_lo[rA[i]][cA[i] * 4 + q] = l;
            }
            *(uint4*)&Bs_hi[rB[i]][cB[i] * 4] = bvh[i];
            *(uint4*)&Bs_lo[rB[i]][cB[i] * 4] = bvl[i];
        }
        __syncthreads();

        // prefetch next tiles (LDGs overlap MMA body)
        if (k0 + BK < K) {
#pragma unroll
            for (int i = 0; i < 2; i++) {
                int gr = row0 + rA[i];
                av[i] = (gr < M)
                    ? *(const float4*)&A[(size_t)gr * K + (k0 + BK) + cA[i] * 4]
                    : make_float4(0.f, 0.f, 0.f, 0.f);
                bvh[i] = *(const uint4*)&Whi[(size_t)(k0 + BK + rB[i]) * 128 + cB[i] * 4];
                bvl[i] = *(const uint4*)&Wlo[(size_t)(k0 + BK + rB[i]) * 128 + cB[i] * 4];
            }
        }

#pragma unroll
        for (int kk = 0; kk < BK; kk += 8) {
            // A fragments (4 m-atoms)
            uint32_t a_hi[4][4], a_lo[4][4];
#pragma unroll
            for (int i = 0; i < 4; i++) {
                int m0 = wm + i * 16 + gid;
                a_hi[i][0] = As_hi[m0    ][kk + tig];
                a_hi[i][1] = As_hi[m0 + 8][kk + tig];
                a_hi[i][2] = As_hi[m0    ][kk + tig + 4];
                a_hi[i][3] = As_hi[m0 + 8][kk + tig + 4];
                a_lo[i][0] = As_lo[m0    ][kk + tig];
                a_lo[i][1] = As_lo[m0 + 8][kk + tig];
                a_lo[i][2] = As_lo[m0    ][kk + tig + 4];
                a_lo[i][3] = As_lo[m0 + 8][kk + tig + 4];
            }
            // B fragments (4 n-atoms)
            uint32_t b_hi[4][2], b_lo[4][2];
#pragma unroll
            for (int j = 0; j < 4; j++) {
                int n0 = wn + j * 8 + gid;
                b_hi[j][0] = Bs_hi[kk + tig    ][n0];
                b_hi[j][1] = Bs_hi[kk + tig + 4][n0];
                b_lo[j][0] = Bs_lo[kk + tig    ][n0];
                b_lo[j][1] = Bs_lo[kk + tig + 4][n0];
            }
#pragma unroll
            for (int i = 0; i < 4; i++)
#pragma unroll
                for (int j = 0; j < 4; j++) {
                    mma_tf32(c[i][j], a_hi[i][0], a_hi[i][1], a_hi[i][2], a_hi[i][3],
                             b_lo[j][0], b_lo[j][1]);
                    mma_tf32(c[i][j], a_lo[i][0], a_lo[i][1], a_lo[i][2], a_lo[i][3],
                             b_hi[j][0], b_hi[j][1]);
                    mma_tf32(c[i][j], a_hi[i][0], a_hi[i][1], a_hi[i][2], a_hi[i][3],
                             b_hi[j][0], b_hi[j][1]);
                }
        }
        __syncthreads();
    }

    // epilogue: scale by inv_out[row]
#pragma unroll
    for (int i = 0; i < 4; i++) {
        int r0 = row0 + wm + i * 16 + gid;
        int r1 = r0 + 8;
        float s0 = (r0 < M) ? inv_out[r0] : 0.f;
        float s1 = (r1 < M) ? inv_out[r1] : 0.f;
#pragma unroll
        for (int j = 0; j < 4; j++) {
            int col = wn + j * 8 + tig * 2;
            if (r0 < M)
                *(float2*)&C[(size_t)r0 * 128 + col] =
                    make_float2(c[i][j][0] * s0, c[i][j][1] * s0);
            if (r1 < M)
                *(float2*)&C[(size_t)r1 * 128 + col] =
                    make_float2(c[i][j][2] * s1, c[i][j][3] * s1);
        }
    }
}

// ---------------- CSR gather with fused epilogue ---------------------------
// blockIdx.y = encoder. One warp per destination node; lane owns 4 floats.
// 8-edge unroll, dual accumulators for deeper MLP + shorter FADD chains.
template <bool RELU>
__global__ void gather_kernel(const float* __restrict__ hbase,
                              const float* __restrict__ bias,
                              float* __restrict__ outbase) {
    const int enc = blockIdx.y;
    int node = (blockIdx.x * blockDim.x + threadIdx.x) >> 5;
    int lane = threadIdx.x & 31;
    if (node >= N_NODES) return;

    const float* __restrict__ h = hbase + (size_t)enc * N_NODES * 128;
    float* __restrict__ out = outbase + (size_t)enc * N_NODES * 128;
    const int* __restrict__ rp = g_row_ptr + enc * (N_NODES + 1);
    const int* __restrict__ es = g_edge_src + enc * MAX_E;

    int beg = rp[node];
    int end = rp[node + 1];

    float4 acc0 = make_float4(0.f, 0.f, 0.f, 0.f);
    float4 acc1 = make_float4(0.f, 0.f, 0.f, 0.f);
    int i = beg;
    for (; i + 8 <= end; i += 8) {
        int s[8];
#pragma unroll
        for (int q = 0; q < 8; q++) s[q] = es[i + q];
        float4 v[8];
#pragma unroll
        for (int q = 0; q < 8; q++)
            v[q] = *(const float4*)&h[(size_t)s[q] * 128 + lane * 4];
        acc0.x += (v[0].x + v[1].x) + (v[2].x + v[3].x);
        acc0.y += (v[0].y + v[1].y) + (v[2].y + v[3].y);
        acc0.z += (v[0].z + v[1].z) + (v[2].z + v[3].z);
        acc0.w += (v[0].w + v[1].w) + (v[2].w + v[3].w);
        acc1.x += (v[4].x + v[5].x) + (v[6].x + v[7].x);
        acc1.y += (v[4].y + v[5].y) + (v[6].y + v[7].y);
        acc1.z += (v[4].z + v[5].z) + (v[6].z + v[7].z);
        acc1.w += (v[4].w + v[5].w) + (v[6].w + v[7].w);
    }
    for (; i < end; i++) {
        int s = es[i];
        float4 v = *(const float4*)&h[(size_t)s * 128 + lane * 4];
        acc0.x += v.x; acc0.y += v.y; acc0.z += v.z; acc0.w += v.w;
    }
    acc0.x += acc1.x; acc0.y += acc1.y; acc0.z += acc1.z; acc0.w += acc1.w;

    float sc = g_inv_in[enc * N_NODES + node];
    float4 bb = *(const float4*)&bias[lane * 4];
    float4 o;
    o.x = acc0.x * sc + bb.x;
    o.y = acc0.y * sc + bb.y;
    o.z = acc0.z * sc + bb.z;
    o.w = acc0.w * sc + bb.w;
    if (RELU) {
        o.x = fmaxf(o.x, 0.f); o.y = fmaxf(o.y, 0.f);
        o.z = fmaxf(o.z, 0.f); o.w = fmaxf(o.w, 0.f);
    }
    *(float4*)&out[(size_t)node * 128 + lane * 4] = o;
}

extern "C" void kernel_launch(void* const* d_in, const int* in_sizes, int n_in,
                              void* d_out, int out_size) {
    GraphPtrs gp;
    FeatPtrs  fp1;
    fp1.p[0]  = (const float*)d_in[0];
    gp.src[0] = (const int*)d_in[1];
    gp.dst[0] = (const int*)d_in[2];
    fp1.p[1]  = (const float*)d_in[3];
    gp.src[1] = (const int*)d_in[4];
    gp.dst[1] = (const int*)d_in[5];
    fp1.p[2]  = (const float*)d_in[6];
    gp.src[2] = (const int*)d_in[7];
    gp.dst[2] = (const int*)d_in[8];
    const float* W1 = (const float*)d_in[9];
    const float* b1 = (const float*)d_in[10];
    const float* W2 = (const float*)d_in[11];
    const float* b2 = (const float*)d_in[12];
    gp.E[0] = in_sizes[1];
    gp.E[1] = in_sizes[4];
    gp.E[2] = in_sizes[7];
    int Emax = gp.E[0];
    if (gp.E[1] > Emax) Emax = gp.E[1];
    if (gp.E[2] > Emax) Emax = gp.E[2];
    float* out = (float*)d_out;

    float *ph, *ptmp;
    uint32_t *w1h, *w1l, *w2h, *w2l;
    cudaGetSymbolAddress((void**)&ph,   g_h);
    cudaGetSymbolAddress((void**)&ptmp, g_tmp);
    cudaGetSymbolAddress((void**)&w1h,  g_W1_hi);
    cudaGetSymbolAddress((void**)&w1l,  g_W1_lo);
    cudaGetSymbolAddress((void**)&w2h,  g_W2_hi);
    cudaGetSymbolAddress((void**)&w2l,  g_W2_lo);

    const int NT = 256;
    dim3 edge_grid((Emax + NT - 1) / NT, NENC);
    dim3 gemm_grid((N_NODES + 127) / 128, NENC);
    dim3 gather_grid((N_NODES * 32 + NT - 1) / NT, NENC);
    const int nblk_3n = (NENC * N_NODES + NT - 1) / NT;

    // pre-split weights once (shared by all 3 encoders)
    split_w_kernel<<<(IN_DIM * 128 + 255) / 256, 256>>>(W1, w1h, w1l, IN_DIM * 128);
    split_w_kernel<<<(HID_DIM * 128 + 255) / 256, 256>>>(W2, w2h, w2l, HID_DIM * 128);

    // CSR build for all 3 graphs
    zero_deg_kernel<<<nblk_3n, NT>>>();
    hist_kernel<<<edge_grid, NT>>>(gp);
    scan_kernel<<<NENC, 1024>>>();
    fill_kernel<<<edge_grid, NT>>>(gp);
    inv_kernel<<<nblk_3n, NT>>>();

    // layer 1 (all encoders per launch)
    gemm_tf32_kernel<IN_DIM><<<gemm_grid, NT>>>(fp1, w1h, w1l, ph, N_NODES);
    gather_kernel<true><<<gather_grid, NT>>>(ph, b1, ptmp);

    // layer 2
    FeatPtrs fp2;
    fp2.p[0] = ptmp;
    fp2.p[1] = ptmp + (size_t)N_NODES * 128;
    fp2.p[2] = ptmp + (size_t)2 * N_NODES * 128;
    gemm_tf32_kernel<HID_DIM><<<gemm_grid, NT>>>(fp2, w2h, w2l, ph, N_NODES);
    gather_kernel<false><<<gather_grid, NT>>>(ph, b2, out);
}

// round 17
// speedup vs baseline: 1.2715x; 1.0214x over previous
#include <cuda_runtime.h>
#include <cuda_bf16.h>
#include <cstdint>

#define N_NODES 50000
#define IN_DIM  512
#define HID_DIM 128
#define MAX_E   1000000
#define NENC    3

// ---------------- scratch (device globals; no allocation allowed) ----------
__device__ float g_h[(size_t)NENC * N_NODES * 128];     // 76.8 MB
__device__ float g_tmp[(size_t)NENC * N_NODES * 128];   // 76.8 MB
__device__ float g_inv_out[NENC * N_NODES];
__device__ float g_inv_in[NENC * N_NODES];
__device__ int   g_deg_out[NENC * N_NODES];
__device__ int   g_deg_in[NENC * N_NODES];
__device__ int   g_row_ptr[NENC * (N_NODES + 1)];
__device__ int   g_cursor[NENC * N_NODES];
__device__ int   g_edge_src[NENC * MAX_E];
// pre-split weights (tf32 hi/lo)
__device__ uint32_t g_W1_hi[IN_DIM * 128],  g_W1_lo[IN_DIM * 128];
__device__ uint32_t g_W2_hi[HID_DIM * 128], g_W2_lo[HID_DIM * 128];

// per-encoder pointer bundle (passed by value through kernel params)
struct GraphPtrs {
    const int*   src[NENC];
    const int*   dst[NENC];
    int          E[NENC];
};
struct FeatPtrs {
    const float* p[NENC];
};

// ---------------- tf32 helpers ---------------------------------------------
__device__ __forceinline__ uint32_t f2tf32(float x) {
    uint32_t r;
    asm("cvt.rna.tf32.f32 %0, %1;" : "=r"(r) : "f"(x));
    return r;
}

__device__ __forceinline__ void split_tf32(float x, uint32_t& hi, uint32_t& lo) {
    hi = f2tf32(x);
    lo = f2tf32(x - __uint_as_float(hi));   // tf32 bits are valid fp32 bits
}

__device__ __forceinline__ void mma_tf32(float c[4],
                                         uint32_t a0, uint32_t a1,
                                         uint32_t a2, uint32_t a3,
                                         uint32_t b0, uint32_t b1) {
    asm volatile(
        "mma.sync.aligned.m16n8k8.row.col.f32.tf32.tf32.f32 "
        "{%0,%1,%2,%3}, {%4,%5,%6,%7}, {%8,%9}, {%0,%1,%2,%3};"
        : "+f"(c[0]), "+f"(c[1]), "+f"(c[2]), "+f"(c[3])
        : "r"(a0), "r"(a1), "r"(a2), "r"(a3), "r"(b0), "r"(b1));
}

// ---------------- weight pre-split (once per launch) -----------------------
__global__ void split_w_kernel(const float* __restrict__ W,
                               uint32_t* __restrict__ hi,
                               uint32_t* __restrict__ lo, int n) {
    int i = blockIdx.x * blockDim.x + threadIdx.x;
    if (i < n) {
        uint32_t h, l;
        split_tf32(W[i], h, l);
        hi[i] = h; lo[i] = l;
    }
}

// ---------------- CSR build (all 3 graphs in one launch each) --------------
__global__ void zero_deg_kernel() {
    int i = blockIdx.x * blockDim.x + threadIdx.x;
    if (i < NENC * N_NODES) { g_deg_out[i] = 0; g_deg_in[i] = 0; }
}

// 4 edges per thread via int4 loads
__global__ void hist_kernel(GraphPtrs gp) {
    int enc = blockIdx.y;
    int E = gp.E[enc];
    int base = (blockIdx.x * blockDim.x + threadIdx.x) * 4;
    if (base >= E) return;
    int* dego = g_deg_out + enc * N_NODES;
    int* degi = g_deg_in  + enc * N_NODES;
    if (base + 4 <= E) {
        int4 s = *(const int4*)&gp.src[enc][base];
        int4 d = *(const int4*)&gp.dst[enc][base];
        atomicAdd(&dego[s.x], 1); atomicAdd(&degi[d.x], 1);
        atomicAdd(&dego[s.y], 1); atomicAdd(&degi[d.y], 1);
        atomicAdd(&dego[s.z], 1); atomicAdd(&degi[d.z], 1);
        atomicAdd(&dego[s.w], 1); atomicAdd(&degi[d.w], 1);
    } else {
        for (int i = base; i < E; i++) {
            atomicAdd(&dego[gp.src[enc][i]], 1);
            atomicAdd(&degi[gp.dst[enc][i]], 1);
        }
    }
}

// one block per graph; chunked exclusive scan of deg_in -> row_ptr, cursor
__global__ void scan_kernel() {
    __shared__ int sums[1024];
    const int enc = blockIdx.x;
    const int* deg = g_deg_in + enc * N_NODES;
    int* rp  = g_row_ptr + enc * (N_NODES + 1);
    int* cur = g_cursor  + enc * N_NODES;

    const int n = N_NODES;
    int tid = threadIdx.x;
    int chunk = (n + 1023) >> 10;
    int start = tid * chunk;
    int end = start + chunk; if (end > n) end = n;
    int local = 0;
    for (int i = start; i < end; i++) local += deg[i];
    sums[tid] = local;
    __syncthreads();
    for (int off = 1; off < 1024; off <<= 1) {
        int v = (tid >= off) ? sums[tid - off] : 0;
        __syncthreads();
        sums[tid] += v;
        __syncthreads();
    }
    int run = (tid == 0) ? 0 : sums[tid - 1];
    for (int i = start; i < end; i++) {
        rp[i]  = run;
        cur[i] = run;
        run += deg[i];
    }
    if (tid == 1023) rp[n] = sums[1023];
}

// 4 edges per thread via int4 loads
__global__ void fill_kernel(GraphPtrs gp) {
    int enc = blockIdx.y;
    int E = gp.E[enc];
    int base = (blockIdx.x * blockDim.x + threadIdx.x) * 4;
    if (base >= E) return;
    int* cur = g_cursor + enc * N_NODES;
    int* es  = g_edge_src + enc * MAX_E;
    if (base + 4 <= E) {
        int4 s = *(const int4*)&gp.src[enc][base];
        int4 d = *(const int4*)&gp.dst[enc][base];
        es[atomicAdd(&cur[d.x], 1)] = s.x;
        es[atomicAdd(&cur[d.y], 1)] = s.y;
        es[atomicAdd(&cur[d.z], 1)] = s.z;
        es[atomicAdd(&cur[d.w], 1)] = s.w;
    } else {
        for (int i = base; i < E; i++) {
            int pos = atomicAdd(&cur[gp.dst[enc][i]], 1);
            es[pos] = gp.src[enc][i];
        }
    }
}

__global__ void inv_kernel() {
    int i = blockIdx.x * blockDim.x + threadIdx.x;
    if (i < NENC * N_NODES) {
        int dout = g_deg_out[i]; if (dout < 1) dout = 1;
        int din  = g_deg_in[i];  if (din  < 1) din  = 1;
        g_inv_out[i] = rsqrtf((float)dout);
        g_inv_in[i]  = rsqrtf((float)din);
    }
}

// ---------------- tf32x3 GEMM: C[M,128] = (A[M,K] @ W[K,128]) * inv_out ----
// BM=128, BN=128, BK=16. 256 threads = 8 warps, warp grid 2(M) x 4(N),
// warp tile 64x32 = 4x4 m16n8k8 atoms. Error-compensated: hh + hl + lh.
// blockIdx.y selects the encoder (A pointer, C slab, inv_out slab).
// __launch_bounds__(256, 2): cap regs at 128 so 2 blocks/SM are resident
// (16 warps) — hides LDS latency in the fragment loads.
template <int K>
__global__ __launch_bounds__(256, 2)
void gemm_tf32_kernel(FeatPtrs fp,
                      const uint32_t* __restrict__ Whi,
                      const uint32_t* __restrict__ Wlo,
                      float* __restrict__ Cbase, int M) {
    constexpr int BM = 128, BK = 16;
    constexpr int AP = 20;    // A row stride (words): conflict-free frag loads
    constexpr int BP = 136;   // B row stride (words)
    __shared__ uint32_t As_hi[BM][AP], As_lo[BM][AP];   // [m][k]
    __shared__ uint32_t Bs_hi[BK][BP], Bs_lo[BK][BP];   // [k][n]

    const int enc = blockIdx.y;
    const float* __restrict__ A = fp.p[enc];
    float* __restrict__ C = Cbase + (size_t)enc * N_NODES * 128;
    const float* __restrict__ inv_out = g_inv_out + enc * N_NODES;

    const int tid  = threadIdx.x;
    const int wid  = tid >> 5;
    const int lane = tid & 31;
    const int gid  = lane >> 2;       // 0..7
    const int tig  = lane & 3;        // 0..3
    const int wm   = (wid & 1) * 64;  // warp M offset
    const int wn   = (wid >> 1) * 32; // warp N offset
    const int row0 = blockIdx.x * BM;

    // global tile-load coords (2 float4/uint4 per thread for each of A, B)
    const int idA0  = tid * 2;
    const int rA[2] = { idA0 >> 2, (idA0 + 1) >> 2 };   // 0..127
    const int cA[2] = { idA0 & 3,  (idA0 + 1) & 3 };    // 0..3  (vec4 idx)
    const int rB[2] = { idA0 >> 5, (idA0 + 1) >> 5 };   // 0..15
    const int cB[2] = { idA0 & 31, (idA0 + 1) & 31 };   // 0..31 (vec4 idx)

    float c[4][4][4];
#pragma unroll
    for (int i = 0; i < 4; i++)
#pragma unroll
        for (int j = 0; j < 4; j++)
#pragma unroll
            for (int q = 0; q < 4; q++) c[i][j][q] = 0.f;

    float4 av[2];
    uint4  bvh[2], bvl[2];
#pragma unroll
    for (int i = 0; i < 2; i++) {
        int gr = row0 + rA[i];
        av[i] = (gr < M) ? *(const float4*)&A[(size_t)gr * K + cA[i] * 4]
                         : make_float4(0.f, 0.f, 0.f, 0.f);
        bvh[i] = *(const uint4*)&Whi[(size_t)rB[i] * 128 + cB[i] * 4];
        bvl[i] = *(const uint4*)&Wlo[(size_t)rB[i] * 128 + cB[i] * 4];
    }

    for (int k0 = 0; k0 < K; k0 += BK) {
        // A: split + store; B: straight copy
#pragma unroll
        for (int i = 0; i < 2; i++) {
            const float va[4] = { av[i].x, av[i].y, av[i].z, av[i].w };
#pragma unroll
            for (int q = 0; q < 4; q++) {
                uint32_t h, l;
                split_tf32(va[q], h, l);
                As_hi[rA[i]][cA[i] * 4 + q] = h;
                As_lo[rA[i]][cA[i] * 4 + q] = l;
            }
            *(uint4*)&Bs_hi[rB[i]][cB[i] * 4] = bvh[i];
            *(uint4*)&Bs_lo[rB[i]][cB[i] * 4] = bvl[i];
        }
        __syncthreads();

        // prefetch next tiles (LDGs overlap MMA body)
        if (k0 + BK < K) {
#pragma unroll
            for (int i = 0; i < 2; i++) {
                int gr = row0 + rA[i];
                av[i] = (gr < M)
                    ? *(const float4*)&A[(size_t)gr * K + (k0 + BK) + cA[i] * 4]
                    : make_float4(0.f, 0.f, 0.f, 0.f);
                bvh[i] = *(const uint4*)&Whi[(size_t)(k0 + BK + rB[i]) * 128 + cB[i] * 4];
                bvl[i] = *(const uint4*)&Wlo[(size_t)(k0 + BK + rB[i]) * 128 + cB[i] * 4];
            }
        }

#pragma unroll
        for (int kk = 0; kk < BK; kk += 8) {
            // A fragments (4 m-atoms)
            uint32_t a_hi[4][4], a_lo[4][4];
#pragma unroll
            for (int i = 0; i < 4; i++) {
                int m0 = wm + i * 16 + gid;
                a_hi[i][0] = As_hi[m0    ][kk + tig];
                a_hi[i][1] = As_hi[m0 + 8][kk + tig];
                a_hi[i][2] = As_hi[m0    ][kk + tig + 4];
                a_hi[i][3] = As_hi[m0 + 8][kk + tig + 4];
                a_lo[i][0] = As_lo[m0    ][kk + tig];
                a_lo[i][1] = As_lo[m0 + 8][kk + tig];
                a_lo[i][2] = As_lo[m0    ][kk + tig + 4];
                a_lo[i][3] = As_lo[m0 + 8][kk + tig + 4];
            }
            // B fragments (4 n-atoms)
            uint32_t b_hi[4][2], b_lo[4][2];
#pragma unroll
            for (int j = 0; j < 4; j++) {
                int n0 = wn + j * 8 + gid;
                b_hi[j][0] = Bs_hi[kk + tig    ][n0];
                b_hi[j][1] = Bs_hi[kk + tig + 4][n0];
                b_lo[j][0] = Bs_lo[kk + tig    ][n0];
                b_lo[j][1] = Bs_lo[kk + tig + 4][n0];
            }
#pragma unroll
            for (int i = 0; i < 4; i++)
#pragma unroll
                for (int j = 0; j < 4; j++) {
                    mma_tf32(c[i][j], a_hi[i][0], a_hi[i][1], a_hi[i][2], a_hi[i][3],
                             b_lo[j][0], b_lo[j][1]);
                    mma_tf32(c[i][j], a_lo[i][0], a_lo[i][1], a_lo[i][2], a_lo[i][3],
                             b_hi[j][0], b_hi[j][1]);
                    mma_tf32(c[i][j], a_hi[i][0], a_hi[i][1], a_hi[i][2], a_hi[i][3],
                             b_hi[j][0], b_hi[j][1]);
                }
        }
        __syncthreads();
    }

    // epilogue: scale by inv_out[row]
#pragma unroll
    for (int i = 0; i < 4; i++) {
        int r0 = row0 + wm + i * 16 + gid;
        int r1 = r0 + 8;
        float s0 = (r0 < M) ? inv_out[r0] : 0.f;
        float s1 = (r1 < M) ? inv_out[r1] : 0.f;
#pragma unroll
        for (int j = 0; j < 4; j++) {
            int col = wn + j * 8 + tig * 2;
            if (r0 < M)
                *(float2*)&C[(size_t)r0 * 128 + col] =
                    make_float2(c[i][j][0] * s0, c[i][j][1] * s0);
            if (r1 < M)
                *(float2*)&C[(size_t)r1 * 128 + col] =
                    make_float2(c[i][j][2] * s1, c[i][j][3] * s1);
        }
    }
}

// ---------------- CSR gather with fused epilogue ---------------------------
// blockIdx.y = encoder. One warp per destination node; lane owns 4 floats.
// 8-edge unroll, dual accumulators for deeper MLP + shorter FADD chains.
template <bool RELU>
__global__ void gather_kernel(const float* __restrict__ hbase,
                              const float* __restrict__ bias,
                              float* __restrict__ outbase) {
    const int enc = blockIdx.y;
    int node = (blockIdx.x * blockDim.x + threadIdx.x) >> 5;
    int lane = threadIdx.x & 31;
    if (node >= N_NODES) return;

    const float* __restrict__ h = hbase + (size_t)enc * N_NODES * 128;
    float* __restrict__ out = outbase + (size_t)enc * N_NODES * 128;
    const int* __restrict__ rp = g_row_ptr + enc * (N_NODES + 1);
    const int* __restrict__ es = g_edge_src + enc * MAX_E;

    int beg = rp[node];
    int end = rp[node + 1];

    float4 acc0 = make_float4(0.f, 0.f, 0.f, 0.f);
    float4 acc1 = make_float4(0.f, 0.f, 0.f, 0.f);
    int i = beg;
    for (; i + 8 <= end; i += 8) {
        int s[8];
#pragma unroll
        for (int q = 0; q < 8; q++) s[q] = es[i + q];
        float4 v[8];
#pragma unroll
        for (int q = 0; q < 8; q++)
            v[q] = *(const float4*)&h[(size_t)s[q] * 128 + lane * 4];
        acc0.x += (v[0].x + v[1].x) + (v[2].x + v[3].x);
        acc0.y += (v[0].y + v[1].y) + (v[2].y + v[3].y);
        acc0.z += (v[0].z + v[1].z) + (v[2].z + v[3].z);
        acc0.w += (v[0].w + v[1].w) + (v[2].w + v[3].w);
        acc1.x += (v[4].x + v[5].x) + (v[6].x + v[7].x);
        acc1.y += (v[4].y + v[5].y) + (v[6].y + v[7].y);
        acc1.z += (v[4].z + v[5].z) + (v[6].z + v[7].z);
        acc1.w += (v[4].w + v[5].w) + (v[6].w + v[7].w);
    }
    for (; i < end; i++) {
        int s = es[i];
        float4 v = *(const float4*)&h[(size_t)s * 128 + lane * 4];
        acc0.x += v.x; acc0.y += v.y; acc0.z += v.z; acc0.w += v.w;
    }
    acc0.x += acc1.x; acc0.y += acc1.y; acc0.z += acc1.z; acc0.w += acc1.w;

    float sc = g_inv_in[enc * N_NODES + node];
    float4 bb = *(const float4*)&bias[lane * 4];
    float4 o;
    o.x = acc0.x * sc + bb.x;
    o.y = acc0.y * sc + bb.y;
    o.z = acc0.z * sc + bb.z;
    o.w = acc0.w * sc + bb.w;
    if (RELU) {
        o.x = fmaxf(o.x, 0.f); o.y = fmaxf(o.y, 0.f);
        o.z = fmaxf(o.z, 0.f); o.w = fmaxf(o.w, 0.f);
    }
    *(float4*)&out[(size_t)node * 128 + lane * 4] = o;
}

extern "C" void kernel_launch(void* const* d_in, const int* in_sizes, int n_in,
                              void* d_out, int out_size) {
    GraphPtrs gp;
    FeatPtrs  fp1;
    fp1.p[0]  = (const float*)d_in[0];
    gp.src[0] = (const int*)d_in[1];
    gp.dst[0] = (const int*)d_in[2];
    fp1.p[1]  = (const float*)d_in[3];
    gp.src[1] = (const int*)d_in[4];
    gp.dst[1] = (const int*)d_in[5];
    fp1.p[2]  = (const float*)d_in[6];
    gp.src[2] = (const int*)d_in[7];
    gp.dst[2] = (const int*)d_in[8];
    const float* W1 = (const float*)d_in[9];
    const float* b1 = (const float*)d_in[10];
    const float* W2 = (const float*)d_in[11];
    const float* b2 = (const float*)d_in[12];
    gp.E[0] = in_sizes[1];
    gp.E[1] = in_sizes[4];
    gp.E[2] = in_sizes[7];
    int Emax = gp.E[0];
    if (gp.E[1] > Emax) Emax = gp.E[1];
    if (gp.E[2] > Emax) Emax = gp.E[2];
    float* out = (float*)d_out;

    float *ph, *ptmp;
    uint32_t *w1h, *w1l, *w2h, *w2l;
    cudaGetSymbolAddress((void**)&ph,   g_h);
    cudaGetSymbolAddress((void**)&ptmp, g_tmp);
    cudaGetSymbolAddress((void**)&w1h,  g_W1_hi);
    cudaGetSymbolAddress((void**)&w1l,  g_W1_lo);
    cudaGetSymbolAddress((void**)&w2h,  g_W2_hi);
    cudaGetSymbolAddress((void**)&w2l,  g_W2_lo);

    const int NT = 256;
    dim3 edge4_grid((Emax + NT * 4 - 1) / (NT * 4), NENC);
    dim3 gemm_grid((N_NODES + 127) / 128, NENC);
    dim3 gather_grid((N_NODES * 32 + NT - 1) / NT, NENC);
    const int nblk_3n = (NENC * N_NODES + NT - 1) / NT;

    // pre-split weights once (shared by all 3 encoders)
    split_w_kernel<<<(IN_DIM * 128 + 255) / 256, 256>>>(W1, w1h, w1l, IN_DIM * 128);
    split_w_kernel<<<(HID_DIM * 128 + 255) / 256, 256>>>(W2, w2h, w2l, HID_DIM * 128);

    // CSR build for all 3 graphs
    zero_deg_kernel<<<nblk_3n, NT>>>();
    hist_kernel<<<edge4_grid, NT>>>(gp);
    scan_kernel<<<NENC, 1024>>>();
    fill_kernel<<<edge4_grid, NT>>>(gp);
    inv_kernel<<<nblk_3n, NT>>>();

    // layer 1 (all encoders per launch)
    gemm_tf32_kernel<IN_DIM><<<gemm_grid, NT>>>(fp1, w1h, w1l, ph, N_NODES);
    gather_kernel<true><<<gather_grid, NT>>>(ph, b1, ptmp);

    // layer 2
    FeatPtrs fp2;
    fp2.p[0] = ptmp;
    fp2.p[1] = ptmp + (size_t)N_NODES * 128;
    fp2.p[2] = ptmp + (size_t)2 * N_NODES * 128;
    gemm_tf32_kernel<HID_DIM><<<gemm_grid, NT>>>(fp2, w2h, w2l, ph, N_NODES);
    gather_kernel<false><<<gather_grid, NT>>>(ph, b2, out);
}